// round 2
// baseline (speedup 1.0000x reference)
#include <cuda_runtime.h>

typedef unsigned long long ull;

// Problem constants
#define B_    16384
#define S_    200
#define N_    6
#define H_    50
#define T_    5
#define NX    56          // operand rows: 50 h + 6 x
#define KT    13          // k-units per role (4 roles cover 52 >= 50)
#define ROLES 4
#define NB    128         // batches per CTA (64 pairs)
#define THREADS 256       // 64 pairs x 4 roles

// SMEM layout in floats.
// wdup[n][role][52 flat(g*13+j)][2 dup]  : n stride 416 fl, role stride 104 fl
#define OFF_W   0
#define W_SIZE  (NX * 416)                 // 23296
#define OFF_B2  (OFF_W + W_SIZE)           // bias dup: [role][52][2] = 416 fl
#define OFF_WL2 (OFF_B2 + 416)             // Wl dup: [m][role][28] = 672 fl
#define OFF_BL  (OFF_WL2 + 672)            // 8 fl
#define OFF_H   (OFF_BL + 8)               // xh buffers: 2 x 56 x 128 fl
#define HBUF    (NX * 128)                 // 7168
#define OFF_PP  (OFF_H + 2 * HBUF)         // pred partials: 64*4*6 ull = 3072 fl
#define SMEM_FL (OFF_PP + 3072)            // 41800 fl = 167.2 KB

// ---------------- packed f32x2 helpers ----------------
__device__ __forceinline__ void ffma2(ull &d, ull a, ull b) {
    asm("fma.rn.f32x2 %0, %1, %2, %0;" : "+l"(d) : "l"(a), "l"(b));
}
__device__ __forceinline__ ull addx2(ull a, ull b) {
    ull r; asm("add.rn.f32x2 %0, %1, %2;" : "=l"(r) : "l"(a), "l"(b)); return r;
}
__device__ __forceinline__ ull pk(float a, float b) {
    ull r; asm("mov.b64 %0, {%1, %2};" : "=l"(r) : "f"(a), "f"(b)); return r;
}
__device__ __forceinline__ float2 up(ull v) {
    float2 r; asm("mov.b64 {%0, %1}, %2;" : "=f"(r.x), "=f"(r.y) : "l"(v)); return r;
}

__device__ __forceinline__ float sigm(float x) {
    return __fdividef(1.0f, 1.0f + __expf(-x));
}
__device__ __forceinline__ float tanha(float x) {
    return __fdividef(2.0f, 1.0f + __expf(-2.0f * x)) - 1.0f;
}

// Stage one weight set (transposed, role-sliced, value-duplicated) into SMEM.
// Operand index n: 0..49 -> h (Whh column n), 50..55 -> x (Wih column n-50).
__device__ void stage_set(float* sm,
                          const float* __restrict__ Wih, const float* __restrict__ Whh,
                          const float* __restrict__ bih, const float* __restrict__ bhh)
{
    for (int idx = threadIdx.x; idx < W_SIZE; idx += THREADS) {
        int n    = idx / 416;
        int rem  = idx % 416;
        int role = rem / 104;
        int r2   = rem % 104;
        int f    = r2 >> 1;          // 0..51 flat = g*13 + j
        int g    = f / KT;
        int j    = f % KT;
        int k    = role * KT + j;
        float v = 0.f;
        if (k < H_) {
            int row = g * H_ + k;
            v = (n < H_) ? Whh[row * H_ + n] : Wih[row * N_ + (n - H_)];
        }
        sm[OFF_W + idx] = v;
    }
    for (int idx = threadIdx.x; idx < 416; idx += THREADS) {
        int role = idx / 104;
        int r2   = idx % 104;
        int f    = r2 >> 1;
        int g    = f / KT;
        int j    = f % KT;
        int k    = role * KT + j;
        float v = 0.f;
        if (k < H_) { int row = g * H_ + k; v = bih[row] + bhh[row]; }
        sm[OFF_B2 + idx] = v;
    }
}

// Gate loop: acc[52] (f32x2 over batch pair) = bias + W^T * xh
__device__ __forceinline__ void gate_loop(const float* __restrict__ sm,
                                          int role, int pair, int cur, ull acc[52])
{
    const ulonglong2* b2 = reinterpret_cast<const ulonglong2*>(sm + OFF_B2 + role * 104);
    #pragma unroll
    for (int q = 0; q < 26; ++q) {
        ulonglong2 t = b2[q];
        acc[2*q]   = t.x;
        acc[2*q+1] = t.y;
    }
    const float* wbase = sm + OFF_W + role * 104;
    const float* hrow  = sm + OFF_H + cur * HBUF + 2 * pair;
    #pragma unroll 2
    for (int n = 0; n < NX; ++n) {
        ull v = *reinterpret_cast<const ull*>(hrow + n * 128);
        const ulonglong2* w = reinterpret_cast<const ulonglong2*>(wbase + n * 416);
        #pragma unroll
        for (int q = 0; q < 26; ++q) {
            ulonglong2 W = w[q];
            ffma2(acc[2*q],   v, W.x);
            ffma2(acc[2*q+1], v, W.y);
        }
    }
}

// Cell epilogue: nonlinearity + c update + h store (into buffer nxt). Returns packed h.
__device__ __forceinline__ void cell_epilogue(float* __restrict__ sm,
                                              int role, int pair, int nxt,
                                              ull acc[52], float cA[KT], float cB[KT],
                                              ull hp[KT])
{
    float* hn = sm + OFF_H + nxt * HBUF + 2 * pair;
    #pragma unroll
    for (int j = 0; j < KT; ++j) {
        float2 ii = up(acc[j]);
        float2 ff = up(acc[KT + j]);
        float2 gg = up(acc[2*KT + j]);
        float2 oo = up(acc[3*KT + j]);

        float cAn = fmaf(sigm(ff.x), cA[j], sigm(ii.x) * tanha(gg.x));
        cA[j] = cAn;
        float hAv = sigm(oo.x) * tanha(cAn);

        float cBn = fmaf(sigm(ff.y), cB[j], sigm(ii.y) * tanha(gg.y));
        cB[j] = cBn;
        float hBv = sigm(oo.y) * tanha(cBn);

        hp[j] = pk(hAv, hBv);
        int k = role * KT + j;
        if (k < H_) *reinterpret_cast<ull*>(hn + k * 128) = hp[j];
    }
}

__global__ void __launch_bounds__(THREADS, 1)
TemPred_kernel(const float* __restrict__ x_seq,
               const float* __restrict__ Wih_e, const float* __restrict__ Whh_e,
               const float* __restrict__ bih_e, const float* __restrict__ bhh_e,
               const float* __restrict__ Wih_d, const float* __restrict__ Whh_d,
               const float* __restrict__ bih_d, const float* __restrict__ bhh_d,
               const float* __restrict__ Wl, const float* __restrict__ bl,
               float* __restrict__ out)
{
    extern __shared__ float sm[];
    const int tid  = threadIdx.x;
    const int pair = tid >> 2;
    const int role = tid & 3;
    const int bA   = blockIdx.x * NB + 2 * pair;
    const int bB   = bA + 1;

    // ---- stage encoder weights, Wl, bl; zero xh buffers ----
    stage_set(sm, Wih_e, Whh_e, bih_e, bhh_e);
    for (int idx = tid; idx < 672; idx += THREADS) {
        int m    = idx / 112;
        int rem  = idx % 112;
        int r    = rem / 28;
        int r3   = rem % 28;
        int j    = r3 >> 1;
        int k    = r * KT + j;
        float v = 0.f;
        if (j < KT && k < H_) v = Wl[m * H_ + k];
        sm[OFF_WL2 + idx] = v;
    }
    if (tid < N_) sm[OFF_BL + tid] = bl[tid];
    for (int idx = tid; idx < 2 * HBUF; idx += THREADS) sm[OFF_H + idx] = 0.f;
    __syncthreads();

    // ---- initial x(0) into buffer 0 rows 50..55 ----
    const float2* xA2 = reinterpret_cast<const float2*>(x_seq + (size_t)bA * (S_ * N_));
    const float2* xB2 = reinterpret_cast<const float2*>(x_seq + (size_t)bB * (S_ * N_));
    float2 xnA[3], xnB[3];
    #pragma unroll
    for (int q = 0; q < 3; ++q) { xnA[q] = xA2[q]; xnB[q] = xB2[q]; }
    if (role == 0) {
        float* xrow = sm + OFF_H + 2 * pair;   // buffer 0
        *reinterpret_cast<ull*>(xrow + 50 * 128) = pk(xnA[0].x, xnB[0].x);
        *reinterpret_cast<ull*>(xrow + 51 * 128) = pk(xnA[0].y, xnB[0].y);
        *reinterpret_cast<ull*>(xrow + 52 * 128) = pk(xnA[1].x, xnB[1].x);
        *reinterpret_cast<ull*>(xrow + 53 * 128) = pk(xnA[1].y, xnB[1].y);
        *reinterpret_cast<ull*>(xrow + 54 * 128) = pk(xnA[2].x, xnB[2].x);
        *reinterpret_cast<ull*>(xrow + 55 * 128) = pk(xnA[2].y, xnB[2].y);
    }
    __syncthreads();

    float cA[KT], cB[KT];
    #pragma unroll
    for (int j = 0; j < KT; ++j) { cA[j] = 0.f; cB[j] = 0.f; }

    ull acc[52];
    ull hp[KT];
    int cur = 0;

    // ================= encoder =================
    for (int t = 0; t < S_; ++t) {
        if (t + 1 < S_) {
            #pragma unroll
            for (int q = 0; q < 3; ++q) {
                xnA[q] = xA2[(t + 1) * 3 + q];
                xnB[q] = xB2[(t + 1) * 3 + q];
            }
        }
        gate_loop(sm, role, pair, cur, acc);
        cell_epilogue(sm, role, pair, cur ^ 1, acc, cA, cB, hp);
        if (role == 0) {
            // x for next step (t<199: x(t+1); t=199: x(199) for decoder input)
            float* xrow = sm + OFF_H + (cur ^ 1) * HBUF + 2 * pair;
            *reinterpret_cast<ull*>(xrow + 50 * 128) = pk(xnA[0].x, xnB[0].x);
            *reinterpret_cast<ull*>(xrow + 51 * 128) = pk(xnA[0].y, xnB[0].y);
            *reinterpret_cast<ull*>(xrow + 52 * 128) = pk(xnA[1].x, xnB[1].x);
            *reinterpret_cast<ull*>(xrow + 53 * 128) = pk(xnA[1].y, xnB[1].y);
            *reinterpret_cast<ull*>(xrow + 54 * 128) = pk(xnA[2].x, xnB[2].x);
            *reinterpret_cast<ull*>(xrow + 55 * 128) = pk(xnA[2].y, xnB[2].y);
        }
        __syncthreads();
        cur ^= 1;
    }

    // ---- re-stage: decoder weights overwrite encoder weights ----
    stage_set(sm, Wih_d, Whh_d, bih_d, bhh_d);
    __syncthreads();

    ull blp[N_];
    #pragma unroll
    for (int m = 0; m < N_; ++m) { float b = sm[OFF_BL + m]; blp[m] = pk(b, b); }

    // ================= decoder =================
    for (int t = 0; t < T_; ++t) {
        gate_loop(sm, role, pair, cur, acc);
        cell_epilogue(sm, role, pair, cur ^ 1, acc, cA, cB, hp);

        // linear head partial over this thread's 13 k's (both batches via f32x2)
        ull* pp = reinterpret_cast<ull*>(sm + OFF_PP) + (pair * ROLES + role) * N_;
        #pragma unroll
        for (int m = 0; m < N_; ++m) {
            const float* wl = sm + OFF_WL2 + m * 112 + role * 28;
            const ulonglong2* wl2 = reinterpret_cast<const ulonglong2*>(wl);
            ull s = pk(0.f, 0.f);
            #pragma unroll
            for (int q = 0; q < 6; ++q) {
                ulonglong2 W = wl2[q];
                ffma2(s, hp[2*q],   W.x);
                ffma2(s, hp[2*q+1], W.y);
            }
            ffma2(s, hp[12], *reinterpret_cast<const ull*>(wl + 24));
            pp[m] = s;
        }
        __syncthreads();

        // reduce 4 role partials -> prediction = next decoder input
        const ull* pp0 = reinterpret_cast<const ull*>(sm + OFF_PP) + pair * ROLES * N_;
        ull xcm[N_];
        #pragma unroll
        for (int m = 0; m < N_; ++m) {
            ull s = addx2(addx2(pp0[m], pp0[N_ + m]), addx2(pp0[2*N_ + m], pp0[3*N_ + m]));
            xcm[m] = addx2(s, blp[m]);
        }
        if (role == 0) {
            float* o1 = out + (size_t)bA * (T_ * N_) + t * N_;
            float* o2 = out + (size_t)bB * (T_ * N_) + t * N_;
            float* xrow = sm + OFF_H + (cur ^ 1) * HBUF + 2 * pair;
            #pragma unroll
            for (int m = 0; m < N_; ++m) {
                float2 v = up(xcm[m]);
                o1[m] = v.x;
                o2[m] = v.y;
                *reinterpret_cast<ull*>(xrow + (50 + m) * 128) = xcm[m];
            }
        }
        __syncthreads();   // protect pp + xh before next iteration
        cur ^= 1;
    }
}

extern "C" void kernel_launch(void* const* d_in, const int* in_sizes, int n_in,
                              void* d_out, int out_size)
{
    (void)in_sizes; (void)n_in; (void)out_size;
    const float* x_seq = (const float*)d_in[0];
    const float* Wih_e = (const float*)d_in[1];
    const float* Whh_e = (const float*)d_in[2];
    const float* bih_e = (const float*)d_in[3];
    const float* bhh_e = (const float*)d_in[4];
    const float* Wih_d = (const float*)d_in[5];
    const float* Whh_d = (const float*)d_in[6];
    const float* bih_d = (const float*)d_in[7];
    const float* bhh_d = (const float*)d_in[8];
    const float* Wl    = (const float*)d_in[9];
    const float* bl    = (const float*)d_in[10];
    float* out = (float*)d_out;

    size_t smem_bytes = SMEM_FL * sizeof(float);   // ~167 KB
    cudaFuncSetAttribute(TemPred_kernel,
                         cudaFuncAttributeMaxDynamicSharedMemorySize,
                         (int)smem_bytes);
    TemPred_kernel<<<B_ / NB, THREADS, smem_bytes>>>(
        x_seq, Wih_e, Whh_e, bih_e, bhh_e,
        Wih_d, Whh_d, bih_d, bhh_d, Wl, bl, out);
}

// round 5
// speedup vs baseline: 2.6326x; 2.6326x over previous
#include <cuda_runtime.h>

typedef unsigned long long ull;

// Problem constants
#define B_    16384
#define S_    200
#define N_    6
#define H_    50
#define T_    5
#define NX    56            // operand rows: 50 h + 6 x
#define MK    5             // hidden units per thread tile
#define KG    10            // k-groups (50/5)
#define NR    4             // batches per thread tile
#define NB    128           // batches per CTA
#define THREADS 320         // KG * 32

// SMEM layout (floats)
#define OFF_W   0                       // W[set][n][kg][20] : 2*56*200
#define W_SET   11200
#define OFF_B   (2 * W_SET)             // 22400: bias[set][kg][20] : 2*200
#define OFF_WL  (OFF_B + 400)           // 22800: WL[kg][m][5] : 300
#define OFF_BL  23104                   // bl[6] (padded, 16B aligned)
#define OFF_XH  23112                   // xh[buf][n][128] : 2*56*128
#define HBUF    (NX * 128)              // 7168
#define OFF_PP  (OFF_XH + 2 * HBUF)     // 37448: pp[kg][m][128] : 10*6*128
#define SMEM_FL (OFF_PP + 7680)         // 45128 fl = 180.5 KB

// ---------------- packed f32x2 + activation helpers ----------------
__device__ __forceinline__ void ffma2(ull &d, ull a, ull b) {
    asm("fma.rn.f32x2 %0, %1, %2, %0;" : "+l"(d) : "l"(a), "l"(b));
}
__device__ __forceinline__ ull pk(float a, float b) {
    ull r; asm("mov.b64 %0, {%1, %2};" : "=l"(r) : "f"(a), "f"(b)); return r;
}
__device__ __forceinline__ float2 up(ull v) {
    float2 r; asm("mov.b64 {%0, %1}, %2;" : "=f"(r.x), "=f"(r.y) : "l"(v)); return r;
}
__device__ __forceinline__ float tap(float x) {
    float r; asm("tanh.approx.f32 %0, %1;" : "=f"(r) : "f"(x)); return r;
}
__device__ __forceinline__ float sigm(float x) {    // 0.5*tanh(x/2)+0.5, 1 MUFU
    return fmaf(tap(0.5f * x), 0.5f, 0.5f);
}

// Stage one weight set into W[set][n][kg][g][j] + bias[set][kg][g][j].
__device__ void stage_set(float* sm, int set,
                          const float* __restrict__ Wih, const float* __restrict__ Whh,
                          const float* __restrict__ bih, const float* __restrict__ bhh)
{
    for (int idx = threadIdx.x; idx < W_SET; idx += THREADS) {
        int n   = idx / 200;
        int rem = idx % 200;          // kg*20 + g*5 + j
        int kg  = rem / 20;
        int r2  = rem % 20;
        int g   = r2 / MK;
        int j   = r2 % MK;
        int row = g * H_ + kg * MK + j;
        float v = (n < H_) ? Whh[row * H_ + n] : Wih[row * N_ + (n - H_)];
        sm[OFF_W + set * W_SET + idx] = v;
    }
    for (int idx = threadIdx.x; idx < 200; idx += THREADS) {
        int kg = idx / 20;
        int r2 = idx % 20;
        int g  = r2 / MK;
        int j  = r2 % MK;
        int row = g * H_ + kg * MK + j;
        sm[OFF_B + set * 200 + idx] = bih[row] + bhh[row];
    }
}

// Gate GEMM: acc[rp*4+b'] (f32x2 over row-pair) = bias + W*xh for this thread's tile.
__device__ __forceinline__ void gate_loop(const float* __restrict__ sm, int set,
                                          int kg, int bg, int cur, ull* __restrict__ acc)
{
    const float4* b4 = reinterpret_cast<const float4*>(sm + OFF_B + set * 200 + kg * 20);
    #pragma unroll
    for (int q = 0; q < 5; ++q) {
        float4 bv = b4[q];
        ull p0 = pk(bv.x, bv.y);
        ull p1 = pk(bv.z, bv.w);
        #pragma unroll
        for (int b = 0; b < NR; ++b) { acc[(2*q)*NR + b] = p0; acc[(2*q+1)*NR + b] = p1; }
    }
    const ulonglong2* wb = reinterpret_cast<const ulonglong2*>(sm + OFF_W + set * W_SET + kg * 20);
    const float* xrow = sm + OFF_XH + cur * HBUF + bg * NR;
    #pragma unroll 2
    for (int n = 0; n < NX; ++n) {
        float4 xv = *reinterpret_cast<const float4*>(xrow + n * 128);
        ull xd0 = pk(xv.x, xv.x), xd1 = pk(xv.y, xv.y);
        ull xd2 = pk(xv.z, xv.z), xd3 = pk(xv.w, xv.w);
        const ulonglong2* w = wb + n * 50;       // 200 floats = 50 ulonglong2 per n
        #pragma unroll
        for (int q = 0; q < 5; ++q) {
            ulonglong2 wp = w[q];                 // rows 4q..4q+3 (two f32x2 pairs)
            ffma2(acc[(2*q)*NR + 0], wp.x, xd0);
            ffma2(acc[(2*q)*NR + 1], wp.x, xd1);
            ffma2(acc[(2*q)*NR + 2], wp.x, xd2);
            ffma2(acc[(2*q)*NR + 3], wp.x, xd3);
            ffma2(acc[(2*q+1)*NR + 0], wp.y, xd0);
            ffma2(acc[(2*q+1)*NR + 1], wp.y, xd1);
            ffma2(acc[(2*q+1)*NR + 2], wp.y, xd2);
            ffma2(acc[(2*q+1)*NR + 3], wp.y, xd3);
        }
    }
}

// Epilogue: gates -> c/h update. hv[j][b'] gets new h. STS h to xh[nxt].
__device__ __forceinline__ void epilogue(float* __restrict__ sm, int kg, int bg, int nxt,
                                         const ull* __restrict__ acc,
                                         float (*c)[NR], float (*hv)[NR])
{
    #pragma unroll
    for (int b = 0; b < NR; ++b) {
        float G[20];
        #pragma unroll
        for (int rp = 0; rp < 10; ++rp) {
            float2 v = up(acc[rp * NR + b]);
            G[2*rp] = v.x; G[2*rp+1] = v.y;
        }
        #pragma unroll
        for (int j = 0; j < MK; ++j) {
            float ig = sigm(G[0*MK + j]);
            float fg = sigm(G[1*MK + j]);
            float gg = tap (G[2*MK + j]);
            float og = sigm(G[3*MK + j]);
            float cn = fmaf(fg, c[j][b], ig * gg);
            c[j][b] = cn;
            hv[j][b] = og * tap(cn);
        }
    }
    float* hd = sm + OFF_XH + nxt * HBUF + bg * NR;
    #pragma unroll
    for (int j = 0; j < MK; ++j) {
        float4 h4 = make_float4(hv[j][0], hv[j][1], hv[j][2], hv[j][3]);
        *reinterpret_cast<float4*>(hd + (kg * MK + j) * 128) = h4;
    }
}

__global__ void __launch_bounds__(THREADS, 1)
TemPred_kernel(const float* __restrict__ x_seq,
               const float* __restrict__ Wih_e, const float* __restrict__ Whh_e,
               const float* __restrict__ bih_e, const float* __restrict__ bhh_e,
               const float* __restrict__ Wih_d, const float* __restrict__ Whh_d,
               const float* __restrict__ bih_d, const float* __restrict__ bhh_d,
               const float* __restrict__ Wl, const float* __restrict__ bl,
               float* __restrict__ out)
{
    extern __shared__ float sm[];
    const int tid = threadIdx.x;
    const int kg  = tid >> 5;          // warp id = k-group
    const int bg  = tid & 31;          // batch group (4 batches)

    // ---- stage weights (both sets), WL, bl; zero xh buffers ----
    stage_set(sm, 0, Wih_e, Whh_e, bih_e, bhh_e);
    stage_set(sm, 1, Wih_d, Whh_d, bih_d, bhh_d);
    for (int idx = tid; idx < 300; idx += THREADS) {
        int g  = idx / 30;             // kg
        int r2 = idx % 30;
        int m  = r2 / MK;
        int j  = r2 % MK;
        sm[OFF_WL + idx] = Wl[m * H_ + g * MK + j];
    }
    if (tid < N_) sm[OFF_BL + tid] = bl[tid];
    for (int idx = tid; idx < 2 * HBUF; idx += THREADS) sm[OFF_XH + idx] = 0.f;
    __syncthreads();

    // ---- x staging duty: warp kg==2 ----
    const int b0 = blockIdx.x * NB + bg * NR;         // first batch of this thread's tile
    float xn[N_][NR];                                  // transposed prefetch regs
    if (kg == 2) {
        #pragma unroll
        for (int b = 0; b < NR; ++b) {
            const float* xb = x_seq + (size_t)(b0 + b) * (S_ * N_);
            #pragma unroll
            for (int m = 0; m < N_; ++m) xn[m][b] = xb[m];
        }
        float* xd = sm + OFF_XH + bg * NR;             // buffer 0
        #pragma unroll
        for (int m = 0; m < N_; ++m)
            *reinterpret_cast<float4*>(xd + (H_ + m) * 128) =
                make_float4(xn[m][0], xn[m][1], xn[m][2], xn[m][3]);
    }
    __syncthreads();

    float c[MK][NR], hv[MK][NR];
    #pragma unroll
    for (int j = 0; j < MK; ++j)
        #pragma unroll
        for (int b = 0; b < NR; ++b) c[j][b] = 0.f;

    ull acc[40];
    int cur = 0;

    // ================= encoder =================
    for (int t = 0; t < S_; ++t) {
        // prefetch x(t+1) (t=199: reload x(199) = decoder input)
        if (kg == 2) {
            int tn = (t + 1 < S_) ? t + 1 : S_ - 1;
            #pragma unroll
            for (int b = 0; b < NR; ++b) {
                const float* xb = x_seq + (size_t)(b0 + b) * (S_ * N_) + tn * N_;
                #pragma unroll
                for (int m = 0; m < N_; ++m) xn[m][b] = xb[m];
            }
        }
        gate_loop(sm, 0, kg, bg, cur, acc);
        epilogue(sm, kg, bg, cur ^ 1, acc, c, hv);
        if (kg == 2) {
            float* xd = sm + OFF_XH + (cur ^ 1) * HBUF + bg * NR;
            #pragma unroll
            for (int m = 0; m < N_; ++m)
                *reinterpret_cast<float4*>(xd + (H_ + m) * 128) =
                    make_float4(xn[m][0], xn[m][1], xn[m][2], xn[m][3]);
        }
        __syncthreads();
        cur ^= 1;
    }

    // ================= decoder =================
    for (int t = 0; t < T_; ++t) {
        gate_loop(sm, 1, kg, bg, cur, acc);
        epilogue(sm, kg, bg, cur ^ 1, acc, c, hv);

        // linear-head partials over this thread's 5 k's, 4 batches
        const float* wlb = sm + OFF_WL + kg * 30;
        float* pp = sm + OFF_PP + kg * 768 + bg * NR;
        #pragma unroll
        for (int m = 0; m < N_; ++m) {
            float s0 = 0.f, s1 = 0.f, s2 = 0.f, s3 = 0.f;
            #pragma unroll
            for (int j = 0; j < MK; ++j) {
                float w = wlb[m * MK + j];
                s0 = fmaf(w, hv[j][0], s0);
                s1 = fmaf(w, hv[j][1], s1);
                s2 = fmaf(w, hv[j][2], s2);
                s3 = fmaf(w, hv[j][3], s3);
            }
            *reinterpret_cast<float4*>(pp + m * 128) = make_float4(s0, s1, s2, s3);
        }
        __syncthreads();

        // reduce over 10 kg partials -> pred; write out + next decoder input
        for (int o = tid; o < 768; o += THREADS) {
            int m = o >> 7;
            int b = o & 127;
            float s = sm[OFF_BL + m];
            #pragma unroll
            for (int g = 0; g < KG; ++g) s += sm[OFF_PP + g * 768 + m * 128 + b];
            out[(size_t)(blockIdx.x * NB + b) * (T_ * N_) + t * N_ + m] = s;
            sm[OFF_XH + (cur ^ 1) * HBUF + (H_ + m) * 128 + b] = s;
        }
        __syncthreads();
        cur ^= 1;
    }
}

extern "C" void kernel_launch(void* const* d_in, const int* in_sizes, int n_in,
                              void* d_out, int out_size)
{
    (void)in_sizes; (void)n_in; (void)out_size;
    const float* x_seq = (const float*)d_in[0];
    const float* Wih_e = (const float*)d_in[1];
    const float* Whh_e = (const float*)d_in[2];
    const float* bih_e = (const float*)d_in[3];
    const float* bhh_e = (const float*)d_in[4];
    const float* Wih_d = (const float*)d_in[5];
    const float* Whh_d = (const float*)d_in[6];
    const float* bih_d = (const float*)d_in[7];
    const float* bhh_d = (const float*)d_in[8];
    const float* Wl    = (const float*)d_in[9];
    const float* bl    = (const float*)d_in[10];
    float* out = (float*)d_out;

    size_t smem_bytes = SMEM_FL * sizeof(float);   // ~180.5 KB
    cudaFuncSetAttribute(TemPred_kernel,
                         cudaFuncAttributeMaxDynamicSharedMemorySize,
                         (int)smem_bytes);
    TemPred_kernel<<<B_ / NB, THREADS, smem_bytes>>>(
        x_seq, Wih_e, Whh_e, bih_e, bhh_e,
        Wih_d, Whh_d, bih_d, bhh_d, Wl, bl, out);
}

// round 8
// speedup vs baseline: 10.4820x; 3.9816x over previous
#include <cuda_runtime.h>
#include <cuda_fp16.h>
#include <cstdint>

typedef uint32_t u32;

// Problem constants
#define B_    16384
#define S_    200
#define N_    6
#define H_    50
#define T_    5
#define NTOT  205            // 200 encoder + 5 decoder steps
#define THREADS 512          // 16 warps: warp = (m-tile 0..7, unit-half 0..1)

// A: xh fp16 [128 rows x 64 K], K = 50 h | 6 x | 1 one | 7 zero. Double buffered.
// W: fp16 [2 sets][256 rows x 64 K], row = gate*64 + unit (units 50..63 zero).
#define SM_A0 0
#define SM_A1 16384
#define SM_W  32768           // 2 * 32768 bytes
#define SM_WL 98304           // Wl [6][50] f32 (1200 B)
#define SM_BL 99520           // bl [6] f32
#define SMEM_TOTAL 99648

#define SWZ(o) ((o) ^ (((o) >> 3) & 0x70))

__device__ __forceinline__ u32 smem_u32(const void* p) {
    u32 a;
    asm("{ .reg .u64 t; cvta.to.shared.u64 t, %1; cvt.u32.u64 %0, t; }" : "=r"(a) : "l"(p));
    return a;
}
__device__ __forceinline__ float tap(float x) {
    float r; asm("tanh.approx.f32 %0, %1;" : "=f"(r) : "f"(x)); return r;
}
__device__ __forceinline__ float sigm(float x) {   // 0.5*tanh(x/2)+0.5
    return fmaf(tap(0.5f * x), 0.5f, 0.5f);
}

#define LDSM4(r, addr) \
    asm volatile("ldmatrix.sync.aligned.m8n8.x4.shared.b16 {%0,%1,%2,%3}, [%4];" \
        : "=r"((r)[0]), "=r"((r)[1]), "=r"((r)[2]), "=r"((r)[3]) : "r"(addr))

#define MMA16816(d, a, bb0, bb1) \
    asm volatile("mma.sync.aligned.m16n8k16.row.col.f32.f16.f16.f32 " \
        "{%0,%1,%2,%3}, {%4,%5,%6,%7}, {%8,%9}, {%0,%1,%2,%3};" \
        : "+f"((d)[0]), "+f"((d)[1]), "+f"((d)[2]), "+f"((d)[3]) \
        : "r"((a)[0]), "r"((a)[1]), "r"((a)[2]), "r"((a)[3]), "r"(bb0), "r"(bb1))

__global__ void __launch_bounds__(THREADS, 1)
TemPred_kernel(const float* __restrict__ x_seq,
               const float* __restrict__ Wih_e, const float* __restrict__ Whh_e,
               const float* __restrict__ bih_e, const float* __restrict__ bhh_e,
               const float* __restrict__ Wih_d, const float* __restrict__ Whh_d,
               const float* __restrict__ bih_d, const float* __restrict__ bhh_d,
               const float* __restrict__ Wl, const float* __restrict__ bl,
               float* __restrict__ out)
{
    extern __shared__ char smem[];
    const int tid  = threadIdx.x;
    const int wid  = tid >> 5;
    const int lane = tid & 31;
    const int mt   = wid >> 1;        // m-tile: rows 16*mt .. +15
    const int uh   = wid & 1;         // unit half: units uh*32 .. +31
    const int b0   = blockIdx.x * 128;
    const u32 sbase = smem_u32(smem);

    // ---- stage weights fp16 (both sets) ----
    for (int idx = tid; idx < 2 * 256 * 64; idx += THREADS) {
        int k    = idx & 63;
        int n    = idx >> 6;          // 0..511
        int set  = n >> 8;
        int rrow = n & 255;
        int g    = rrow >> 6, u = rrow & 63;
        float v = 0.f;
        if (u < H_) {
            int rw = g * H_ + u;
            if (k < H_)      v = (set ? Whh_d : Whh_e)[rw * H_ + k];
            else if (k < 56) v = (set ? Wih_d : Wih_e)[rw * N_ + (k - 50)];
            else if (k == 56) v = set ? (bih_d[rw] + bhh_d[rw]) : (bih_e[rw] + bhh_e[rw]);
        }
        *(__half*)(smem + SM_W + (set << 15) + SWZ((u32)(rrow * 128 + 2 * k))) = __float2half(v);
    }
    for (int i = tid; i < 300; i += THREADS) ((float*)(smem + SM_WL))[i] = Wl[i];
    if (tid < N_) ((float*)(smem + SM_BL))[tid] = bl[tid];
    // zero A0 + A1
    for (int i = tid; i < 8192; i += THREADS) ((u32*)smem)[i] = 0u;
    __syncthreads();

    // bias-one col 56 (both buffers) + x(0) into A0
    if (tid < 128) {
        *(__half*)(smem + SM_A0 + SWZ((u32)(tid * 128 + 112))) = __float2half(1.0f);
        *(__half*)(smem + SM_A1 + SWZ((u32)(tid * 128 + 112))) = __float2half(1.0f);
        const float* xp = x_seq + (size_t)(b0 + tid) * (S_ * N_);
        *(__half2*)(smem + SM_A0 + SWZ((u32)(tid * 128 + 100))) = __floats2half2_rn(xp[0], xp[1]);
        *(__half2*)(smem + SM_A0 + SWZ((u32)(tid * 128 + 104))) = __floats2half2_rn(xp[2], xp[3]);
        *(__half2*)(smem + SM_A0 + SWZ((u32)(tid * 128 + 108))) = __floats2half2_rn(xp[4], xp[5]);
    }
    __syncthreads();

    float c[16];
    #pragma unroll
    for (int i = 0; i < 16; ++i) c[i] = 0.f;

    // per-thread geometry
    const int q     = lane >> 3;
    const u32 rowA  = (u32)(mt * 16 + (lane & 7) + ((q & 1) << 3));
    const u32 kbA   = (u32)((q >> 1) << 4);
    const int csel  = lane & 3;                 // column pair selector
    const int r0    = mt * 16 + (lane >> 2);    // first D row
    const float* Wls = (const float*)(smem + SM_WL);
    const float* bls = (const float*)(smem + SM_BL);

    int cur = 0;
    for (int t = 0; t < NTOT; ++t) {
        // prefetch next x (encoder only)
        float xv0, xv1, xv2, xv3, xv4, xv5;
        const bool xduty = (tid < 128) && (t < S_);
        if (xduty) {
            int tn = (t + 1 < S_) ? t + 1 : S_ - 1;
            const float* xp = x_seq + (size_t)(b0 + tid) * (S_ * N_) + tn * N_;
            xv0 = xp[0]; xv1 = xp[1]; xv2 = xp[2]; xv3 = xp[3]; xv4 = xp[4]; xv5 = xp[5];
        }

        const u32 abase = sbase + (cur ? SM_A1 : SM_A0);
        char* An = smem + (cur ? SM_A0 : SM_A1);
        const u32 wbase = sbase + SM_W + ((t >= S_) ? 32768u : 0u);

        // A fragments: 4 k-chunks of 16
        u32 a[16];
        #pragma unroll
        for (int kc = 0; kc < 4; ++kc)
            LDSM4(a + 4 * kc, abase + SWZ(rowA * 128 + kbA + 32 * kc));

        #pragma unroll
        for (int oct = 0; oct < 4; ++oct) {
            const int u0 = uh * 32 + oct * 8;
            if (u0 >= H_) continue;             // fully-padded octet (uh=1, oct=3)

            // B fragments: 4 gates x 8 regs (k-chunks 0..3)
            u32 bfr[4][8];
            #pragma unroll
            for (int g = 0; g < 4; ++g) {
                const u32 rowB = (u32)(g * 64 + u0 + (lane & 7));
                const u32 kbB  = (u32)((lane >> 3) << 4);
                LDSM4(bfr[g] + 0, wbase + SWZ(rowB * 128 + kbB));
                LDSM4(bfr[g] + 4, wbase + SWZ(rowB * 128 + 64 + kbB));
            }

            float d[4][4];
            #pragma unroll
            for (int g = 0; g < 4; ++g) {
                d[g][0] = 0.f; d[g][1] = 0.f; d[g][2] = 0.f; d[g][3] = 0.f;
                #pragma unroll
                for (int kc = 0; kc < 4; ++kc)
                    MMA16816(d[g], a + 4 * kc, bfr[g][2 * kc], bfr[g][2 * kc + 1]);
            }

            // epilogue: 4 cells/thread (2 units x 2 rows), all gates thread-local
            float h[4];
            #pragma unroll
            for (int e = 0; e < 4; ++e) {
                float iv = sigm(d[0][e]);
                float fv = sigm(d[1][e]);
                float gv = tap (d[2][e]);
                float ov = sigm(d[3][e]);
                float cn = fmaf(fv, c[oct * 4 + e], iv * gv);
                c[oct * 4 + e] = cn;
                h[e] = ov * tap(cn);
            }
            const int uA = u0 + 2 * csel;
            if (uA < H_) {                       // pair (uA, uA+1) valid (50 is even)
                *(__half2*)(An + SWZ((u32)(r0 * 128 + 2 * uA)))       = __floats2half2_rn(h[0], h[1]);
                *(__half2*)(An + SWZ((u32)((r0 + 8) * 128 + 2 * uA))) = __floats2half2_rn(h[2], h[3]);
            }
        }

        if (t < S_) {
            if (xduty) {
                *(__half2*)(An + SWZ((u32)(tid * 128 + 100))) = __floats2half2_rn(xv0, xv1);
                *(__half2*)(An + SWZ((u32)(tid * 128 + 104))) = __floats2half2_rn(xv2, xv3);
                *(__half2*)(An + SWZ((u32)(tid * 128 + 108))) = __floats2half2_rn(xv4, xv5);
            }
        } else {
            // decoder: head reads h from An after all h stores
            __syncthreads();
            const int dt = t - S_;
            for (int task = tid; task < 768; task += THREADS) {
                const int row = task & 127;
                const int m   = task >> 7;
                float s = bls[m];
                #pragma unroll
                for (int j = 0; j < 25; ++j) {
                    __half2 hh = *(__half2*)(An + SWZ((u32)(row * 128 + 4 * j)));
                    float2 hf = __half22float2(hh);
                    s = fmaf(Wls[m * H_ + 2 * j],     hf.x, s);
                    s = fmaf(Wls[m * H_ + 2 * j + 1], hf.y, s);
                }
                out[(size_t)(b0 + row) * (T_ * N_) + dt * N_ + m] = s;
                *(__half*)(An + SWZ((u32)(row * 128 + 2 * (50 + m)))) = __float2half(s);
            }
        }

        __syncthreads();
        cur ^= 1;
    }
}

extern "C" void kernel_launch(void* const* d_in, const int* in_sizes, int n_in,
                              void* d_out, int out_size)
{
    (void)in_sizes; (void)n_in; (void)out_size;
    const float* x_seq = (const float*)d_in[0];
    const float* Wih_e = (const float*)d_in[1];
    const float* Whh_e = (const float*)d_in[2];
    const float* bih_e = (const float*)d_in[3];
    const float* bhh_e = (const float*)d_in[4];
    const float* Wih_d = (const float*)d_in[5];
    const float* Whh_d = (const float*)d_in[6];
    const float* bih_d = (const float*)d_in[7];
    const float* bhh_d = (const float*)d_in[8];
    const float* Wl    = (const float*)d_in[9];
    const float* bl    = (const float*)d_in[10];
    float* out = (float*)d_out;

    cudaFuncSetAttribute(TemPred_kernel,
                         cudaFuncAttributeMaxDynamicSharedMemorySize, SMEM_TOTAL);
    TemPred_kernel<<<B_ / 128, THREADS, SMEM_TOTAL>>>(
        x_seq, Wih_e, Whh_e, bih_e, bhh_e,
        Wih_d, Whh_d, bih_d, bhh_d, Wl, bl, out);
}

// round 10
// speedup vs baseline: 12.8665x; 1.2275x over previous
#include <cuda_runtime.h>
#include <cuda_fp16.h>
#include <cstdint>

typedef uint32_t u32;

// Problem constants
#define B_    16384
#define S_    200
#define N_    6
#define H_    50
#define T_    5
#define NTOT  205            // 200 encoder + 5 decoder steps
#define THREADS 512          // 16 warps: warp = (m-tile 0..7, unit-half 0..1)

// A: xh fp16 [128 rows x 64 K], K = 50 h | 6 x | 1 one | 7 zero. Double buffered.
// W: fp16 [2 sets][256 rows x 64 K], row = gate*64 + unit (units 50..63 zero).
#define SM_A0 0
#define SM_A1 16384
#define SM_W  32768           // 2 * 32768 bytes
#define SM_WL 98304           // Wl [6][50] f32 (1200 B)
#define SM_BL 99520           // bl [6] f32
#define SMEM_TOTAL 99648

#define SWZ(o) ((o) ^ (((o) >> 3) & 0x70))

// pair barrier: 2 warps (64 threads), ids 1..8
#define BARP() asm volatile("bar.sync %0, 64;" :: "r"(mt + 1) : "memory")

__device__ __forceinline__ u32 smem_u32(const void* p) {
    u32 a;
    asm("{ .reg .u64 t; cvta.to.shared.u64 t, %1; cvt.u32.u64 %0, t; }" : "=r"(a) : "l"(p));
    return a;
}
__device__ __forceinline__ float tap(float x) {
    float r; asm("tanh.approx.f32 %0, %1;" : "=f"(r) : "f"(x)); return r;
}
__device__ __forceinline__ float sigm(float x) {   // 0.5*tanh(x/2)+0.5
    return fmaf(tap(0.5f * x), 0.5f, 0.5f);
}

#define LDSM4(r, addr) \
    asm volatile("ldmatrix.sync.aligned.m8n8.x4.shared.b16 {%0,%1,%2,%3}, [%4];" \
        : "=r"((r)[0]), "=r"((r)[1]), "=r"((r)[2]), "=r"((r)[3]) : "r"(addr))

#define MMA16816(d, a, bb0, bb1) \
    asm volatile("mma.sync.aligned.m16n8k16.row.col.f32.f16.f16.f32 " \
        "{%0,%1,%2,%3}, {%4,%5,%6,%7}, {%8,%9}, {%0,%1,%2,%3};" \
        : "+f"((d)[0]), "+f"((d)[1]), "+f"((d)[2]), "+f"((d)[3]) \
        : "r"((a)[0]), "r"((a)[1]), "r"((a)[2]), "r"((a)[3]), "r"(bb0), "r"(bb1))

__global__ void __launch_bounds__(THREADS, 1)
TemPred_kernel(const float* __restrict__ x_seq,
               const float* __restrict__ Wih_e, const float* __restrict__ Whh_e,
               const float* __restrict__ bih_e, const float* __restrict__ bhh_e,
               const float* __restrict__ Wih_d, const float* __restrict__ Whh_d,
               const float* __restrict__ bih_d, const float* __restrict__ bhh_d,
               const float* __restrict__ Wl, const float* __restrict__ bl,
               float* __restrict__ out)
{
    extern __shared__ char smem[];
    const int tid  = threadIdx.x;
    const int wid  = tid >> 5;
    const int lane = tid & 31;
    const int mt   = wid >> 1;        // m-tile: rows 16*mt .. +15 (pair id)
    const int uh   = wid & 1;         // unit half: units uh*32 .. +31
    const int b0   = blockIdx.x * 128;
    const u32 sbase = smem_u32(smem);

    // ---- stage weights fp16 (both sets) ----
    for (int idx = tid; idx < 2 * 256 * 64; idx += THREADS) {
        int k    = idx & 63;
        int n    = idx >> 6;          // 0..511
        int set  = n >> 8;
        int rrow = n & 255;
        int g    = rrow >> 6, u = rrow & 63;
        float v = 0.f;
        if (u < H_) {
            int rw = g * H_ + u;
            if (k < H_)      v = (set ? Whh_d : Whh_e)[rw * H_ + k];
            else if (k < 56) v = (set ? Wih_d : Wih_e)[rw * N_ + (k - 50)];
            else if (k == 56) v = set ? (bih_d[rw] + bhh_d[rw]) : (bih_e[rw] + bhh_e[rw]);
        }
        *(__half*)(smem + SM_W + (set << 15) + SWZ((u32)(rrow * 128 + 2 * k))) = __float2half(v);
    }
    for (int i = tid; i < 300; i += THREADS) ((float*)(smem + SM_WL))[i] = Wl[i];
    if (tid < N_) ((float*)(smem + SM_BL))[tid] = bl[tid];
    // zero A0 + A1
    for (int i = tid; i < 8192; i += THREADS) ((u32*)smem)[i] = 0u;
    __syncthreads();

    // per-thread geometry
    const int q     = lane >> 3;
    const u32 rowA  = (u32)(mt * 16 + (lane & 7) + ((q & 1) << 3));
    const u32 kbA   = (u32)((q >> 1) << 4);
    const int csel  = lane & 3;                 // column pair selector
    const int r0    = mt * 16 + (lane >> 2);    // first D row
    const float* Wls = (const float*)(smem + SM_WL);
    const float* bls = (const float*)(smem + SM_BL);

    // x staging duty: pair-local — uh==0, lane<16 handles row 16*mt+lane
    const bool xduty = (uh == 0) && (lane < 16);
    const int  xrow  = mt * 16 + lane;

    // bias-one col 56 (both buffers) + x(0) into A0
    if (tid < 128) {
        *(__half*)(smem + SM_A0 + SWZ((u32)(tid * 128 + 112))) = __float2half(1.0f);
        *(__half*)(smem + SM_A1 + SWZ((u32)(tid * 128 + 112))) = __float2half(1.0f);
    }
    if (xduty) {
        const float* xp = x_seq + (size_t)(b0 + xrow) * (S_ * N_);
        *(__half2*)(smem + SM_A0 + SWZ((u32)(xrow * 128 + 100))) = __floats2half2_rn(xp[0], xp[1]);
        *(__half2*)(smem + SM_A0 + SWZ((u32)(xrow * 128 + 104))) = __floats2half2_rn(xp[2], xp[3]);
        *(__half2*)(smem + SM_A0 + SWZ((u32)(xrow * 128 + 108))) = __floats2half2_rn(xp[4], xp[5]);
    }
    __syncthreads();

    float c[16];
    #pragma unroll
    for (int i = 0; i < 16; ++i) c[i] = 0.f;

    int cur = 0;
    for (int t = 0; t < NTOT; ++t) {
        // prefetch next x (encoder only)
        float xv0, xv1, xv2, xv3, xv4, xv5;
        if (xduty && t < S_) {
            int tn = (t + 1 < S_) ? t + 1 : S_ - 1;
            const float* xp = x_seq + (size_t)(b0 + xrow) * (S_ * N_) + tn * N_;
            xv0 = xp[0]; xv1 = xp[1]; xv2 = xp[2]; xv3 = xp[3]; xv4 = xp[4]; xv5 = xp[5];
        }

        const u32 abase = sbase + (cur ? SM_A1 : SM_A0);
        char* An = smem + (cur ? SM_A0 : SM_A1);
        const u32 wbase = sbase + SM_W + ((t >= S_) ? 32768u : 0u);

        // A fragments: 4 k-chunks of 16
        u32 a[16];
        #pragma unroll
        for (int kc = 0; kc < 4; ++kc)
            LDSM4(a + 4 * kc, abase + SWZ(rowA * 128 + kbA + 32 * kc));

        #pragma unroll
        for (int oct = 0; oct < 4; ++oct) {
            const int u0 = uh * 32 + oct * 8;
            if (u0 >= H_) continue;             // fully-padded octet (uh=1, oct=3)

            // B fragments: 4 gates x 8 regs (k-chunks 0..3)
            u32 bfr[4][8];
            #pragma unroll
            for (int g = 0; g < 4; ++g) {
                const u32 rowB = (u32)(g * 64 + u0 + (lane & 7));
                const u32 kbB  = (u32)((lane >> 3) << 4);
                LDSM4(bfr[g] + 0, wbase + SWZ(rowB * 128 + kbB));
                LDSM4(bfr[g] + 4, wbase + SWZ(rowB * 128 + 64 + kbB));
            }

            float d[4][4];
            #pragma unroll
            for (int g = 0; g < 4; ++g) {
                d[g][0] = 0.f; d[g][1] = 0.f; d[g][2] = 0.f; d[g][3] = 0.f;
                #pragma unroll
                for (int kc = 0; kc < 4; ++kc)
                    MMA16816(d[g], a + 4 * kc, bfr[g][2 * kc], bfr[g][2 * kc + 1]);
            }

            // epilogue: 4 cells/thread (2 units x 2 rows), all gates thread-local
            float h[4];
            #pragma unroll
            for (int e = 0; e < 4; ++e) {
                float iv = sigm(d[0][e]);
                float fv = sigm(d[1][e]);
                float gv = tap (d[2][e]);
                float ov = sigm(d[3][e]);
                float cn = fmaf(fv, c[oct * 4 + e], iv * gv);
                c[oct * 4 + e] = cn;
                h[e] = ov * tap(cn);
            }
            const int uA = u0 + 2 * csel;
            if (uA < H_) {                       // pair (uA, uA+1) valid (50 is even)
                *(__half2*)(An + SWZ((u32)(r0 * 128 + 2 * uA)))       = __floats2half2_rn(h[0], h[1]);
                *(__half2*)(An + SWZ((u32)((r0 + 8) * 128 + 2 * uA))) = __floats2half2_rn(h[2], h[3]);
            }
        }

        if (t < S_) {
            if (xduty) {
                *(__half2*)(An + SWZ((u32)(xrow * 128 + 100))) = __floats2half2_rn(xv0, xv1);
                *(__half2*)(An + SWZ((u32)(xrow * 128 + 104))) = __floats2half2_rn(xv2, xv3);
                *(__half2*)(An + SWZ((u32)(xrow * 128 + 108))) = __floats2half2_rn(xv4, xv5);
            }
        } else {
            // decoder: head reads h from An after pair's h stores are visible
            BARP();
            const int dt = t - S_;
            const int pt = uh * 32 + lane;       // 0..63 within pair
            for (int task = pt; task < 96; task += 64) {
                const int rloc = task & 15;
                const int m    = task >> 4;
                const int row  = mt * 16 + rloc;
                float s = bls[m];
                #pragma unroll
                for (int j = 0; j < 25; ++j) {
                    __half2 hh = *(__half2*)(An + SWZ((u32)(row * 128 + 4 * j)));
                    float2 hf = __half22float2(hh);
                    s = fmaf(Wls[m * H_ + 2 * j],     hf.x, s);
                    s = fmaf(Wls[m * H_ + 2 * j + 1], hf.y, s);
                }
                out[(size_t)(b0 + row) * (T_ * N_) + dt * N_ + m] = s;
                *(__half*)(An + SWZ((u32)(row * 128 + 2 * (50 + m)))) = __float2half(s);
            }
        }

        BARP();                                   // pair-local step boundary
        cur ^= 1;
    }
}

extern "C" void kernel_launch(void* const* d_in, const int* in_sizes, int n_in,
                              void* d_out, int out_size)
{
    (void)in_sizes; (void)n_in; (void)out_size;
    const float* x_seq = (const float*)d_in[0];
    const float* Wih_e = (const float*)d_in[1];
    const float* Whh_e = (const float*)d_in[2];
    const float* bih_e = (const float*)d_in[3];
    const float* bhh_e = (const float*)d_in[4];
    const float* Wih_d = (const float*)d_in[5];
    const float* Whh_d = (const float*)d_in[6];
    const float* bih_d = (const float*)d_in[7];
    const float* bhh_d = (const float*)d_in[8];
    const float* Wl    = (const float*)d_in[9];
    const float* bl    = (const float*)d_in[10];
    float* out = (float*)d_out;

    cudaFuncSetAttribute(TemPred_kernel,
                         cudaFuncAttributeMaxDynamicSharedMemorySize, SMEM_TOTAL);
    TemPred_kernel<<<B_ / 128, THREADS, SMEM_TOTAL>>>(
        x_seq, Wih_e, Whh_e, bih_e, bhh_e,
        Wih_d, Whh_d, bih_d, bhh_d, Wl, bl, out);
}